// round 12
// baseline (speedup 1.0000x reference)
#include <cuda_runtime.h>
#include <cuda_fp16.h>
#include <cstdint>

#define BB 8
#define SS 2048
#define DD 1024
#define HH 64
#define MM (BB*SS)

// Scratch (fp16): Q pre-scaled by log2e/32; K,V hi-only
__device__ __align__(16) __half g_Qh[MM*HH];
__device__ __align__(16) __half g_Kh[MM*HH];
__device__ __align__(16) __half g_Vh[MM*HH];

// ---------------------------------------------------------------------------
// helpers
// ---------------------------------------------------------------------------
__device__ __forceinline__ uint32_t pack2h(float lo, float hi) {
    uint32_t r;
    asm("cvt.rn.f16x2.f32 %0, %1, %2;" : "=r"(r) : "f"(hi), "f"(lo));
    return r;
}

__device__ __forceinline__ void ldm_x4(uint32_t* r, uint32_t addr) {
    asm volatile("ldmatrix.sync.aligned.m8n8.x4.shared.b16 {%0,%1,%2,%3}, [%4];"
                 : "=r"(r[0]), "=r"(r[1]), "=r"(r[2]), "=r"(r[3]) : "r"(addr));
}
__device__ __forceinline__ void ldm_x4_t(uint32_t* r, uint32_t addr) {
    asm volatile("ldmatrix.sync.aligned.m8n8.x4.trans.shared.b16 {%0,%1,%2,%3}, [%4];"
                 : "=r"(r[0]), "=r"(r[1]), "=r"(r[2]), "=r"(r[3]) : "r"(addr));
}

__device__ __forceinline__ void cp16(uint32_t dst, const void* src) {
    asm volatile("cp.async.cg.shared.global [%0], [%1], 16;"
                 :: "r"(dst), "l"(src) : "memory");
}
#define CP_COMMIT() asm volatile("cp.async.commit_group;" ::: "memory")
#define CP_WAIT0()  asm volatile("cp.async.wait_group 0;" ::: "memory")

// smem fp16 tiles: row stride 144 bytes (72 halves) -> ldmatrix conflict-free
#define LDB 144

__device__ __forceinline__ uint32_t ldm_addr(uint32_t base, int row0, int col0) {
    int l = threadIdx.x & 31;
    int r = row0 + (l & 7) + ((l >> 3) & 1) * 8;
    int c = col0 + (l >> 4) * 8;
    return base + r * LDB + c * 2;
}
__device__ __forceinline__ uint32_t ldm_addr_b(uint32_t base, int row0, int col0) {
    int l = threadIdx.x & 31;
    int r = row0 + (l & 7) + (l >> 4) * 8;
    int c = col0 + ((l >> 3) & 1) * 8;
    return base + r * LDB + c * 2;
}

__device__ __forceinline__ void mma_f16(float* d, const uint32_t* a, const uint32_t* b) {
    asm volatile(
        "mma.sync.aligned.m16n8k16.row.col.f32.f16.f16.f32 "
        "{%0,%1,%2,%3}, {%4,%5,%6,%7}, {%8,%9}, {%0,%1,%2,%3};"
        : "+f"(d[0]), "+f"(d[1]), "+f"(d[2]), "+f"(d[3])
        : "r"(a[0]), "r"(a[1]), "r"(a[2]), "r"(a[3]), "r"(b[0]), "r"(b[1]));
}

// 2^x via magic-round + deg-4 Taylor. No clamp: inputs bounded (masked = -126).
__device__ __forceinline__ float fast_exp2(float x) {
    float r = x + 12582912.0f;
    int ik = __float_as_int(r) - 0x4B400000;
    float f = x - (r - 12582912.0f);
    float p = fmaf(0.0096180f, f, 0.0555041f);
    p = fmaf(p, f, 0.2402265f);
    p = fmaf(p, f, 0.6931472f);
    p = fmaf(p, f, 1.0f);
    return __int_as_float(__float_as_int(p) + (ik << 23));
}

// ---------------------------------------------------------------------------
// proj: Q,K,V = Xh @ Wh^T (1-term fp16), W converted f32->f16 inline.
// CTA = 64 rows, 256 thr, 256 CTAs. Warps 2m x 4n. Outputs fp16 hi-only.
// ---------------------------------------------------------------------------
#define PTM 64
#define PXH 0
#define PWH 9216
#define PTOT 36864

__global__ __launch_bounds__(256) void proj_tc(const float* __restrict__ X,
                                               const float* __restrict__ Wq,
                                               const float* __restrict__ Wk,
                                               const float* __restrict__ Wv) {
    extern __shared__ char sm[];
    const uint32_t sb = (uint32_t)__cvta_generic_to_shared(sm);
    const int tid = threadIdx.x, wid = tid >> 5, lane = tid & 31;
    const int g = lane >> 2, t = lane & 3;
    const int wm = wid >> 2, wn = wid & 3;
    const int m0 = blockIdx.x * PTM;

    float acc[3][2][2][4];
    #pragma unroll
    for (int a = 0; a < 3; a++)
        #pragma unroll
        for (int b = 0; b < 2; b++)
            #pragma unroll
            for (int c = 0; c < 2; c++)
                #pragma unroll
                for (int d = 0; d < 4; d++) acc[a][b][c][d] = 0.f;

    for (int kc = 0; kc < 16; kc++) {
        const int kbase = kc * 64;
        // X chunk: 64 rows x 64 f32 -> rn f16
        #pragma unroll
        for (int i = 0; i < 4; i++) {
            int id = tid + i * 256;
            int row = id >> 4, c4 = id & 15;
            float4 v = *reinterpret_cast<const float4*>(
                X + (size_t)(m0 + row) * DD + kbase + c4 * 4);
            uint32_t off = row * LDB + c4 * 8;
            *reinterpret_cast<uint32_t*>(sm + PXH + off)     = pack2h(v.x, v.y);
            *reinterpret_cast<uint32_t*>(sm + PXH + off + 4) = pack2h(v.z, v.w);
        }
        // W chunk: 192 rows x 64 f32 -> rn f16 inline (rows: 0-63 Q, 64-127 K, 128-191 V)
        #pragma unroll
        for (int i = 0; i < 12; i++) {
            int id = tid + i * 256;
            int row = id >> 4, c4 = id & 15;
            const float* Wp = (row < 64) ? Wq : ((row < 128) ? Wk : Wv);
            int wr = row & 63;
            float4 v = *reinterpret_cast<const float4*>(
                Wp + (size_t)wr * DD + kbase + c4 * 4);
            uint32_t off = row * LDB + c4 * 8;
            *reinterpret_cast<uint32_t*>(sm + PWH + off)     = pack2h(v.x, v.y);
            *reinterpret_cast<uint32_t*>(sm + PWH + off + 4) = pack2h(v.z, v.w);
        }
        __syncthreads();

        #pragma unroll
        for (int ks = 0; ks < 4; ks++) {
            uint32_t ah[2][4];
            #pragma unroll
            for (int fm = 0; fm < 2; fm++)
                ldm_x4(ah[fm], ldm_addr(sb + PXH, wm * 32 + fm * 16, ks * 16));
            #pragma unroll
            for (int mat = 0; mat < 3; mat++) {
                uint32_t bh[4];
                ldm_x4(bh, ldm_addr_b(sb + PWH, mat * 64 + wn * 16, ks * 16));
                #pragma unroll
                for (int fm = 0; fm < 2; fm++)
                    #pragma unroll
                    for (int fn = 0; fn < 2; fn++)
                        mma_f16(acc[mat][fm][fn], ah[fm], &bh[fn * 2]);
            }
        }
        __syncthreads();
    }

    // epilogue: all outputs fp16 hi-only; Q scaled by log2e/32
    #pragma unroll
    for (int mat = 0; mat < 3; mat++) {
        __half* gh = (mat == 0) ? g_Qh : ((mat == 1) ? g_Kh : g_Vh);
        const float scl = (mat == 0) ? (1.44269504f / 32.0f) : 1.0f;
        #pragma unroll
        for (int fm = 0; fm < 2; fm++)
            #pragma unroll
            for (int fn = 0; fn < 2; fn++) {
                const float* c = acc[mat][fm][fn];
                int r0 = m0 + wm * 32 + fm * 16 + g;
                int col = wn * 16 + fn * 8 + t * 2;
                reinterpret_cast<uint32_t*>(gh)[((size_t)r0 * HH + col) >> 1] =
                    pack2h(c[0] * scl, c[1] * scl);
                reinterpret_cast<uint32_t*>(gh)[((size_t)(r0 + 8) * HH + col) >> 1] =
                    pack2h(c[2] * scl, c[3] * scl);
            }
    }
}

// ---------------------------------------------------------------------------
// attn: flash attention (fp16 hi-only), no-max softmax, register P,
// Q fragments hoisted into registers, 2-stage cp.async K/V pipeline.
// 256 CTAs balanced, 256 thr, warps 4 qw x 2 kw.
// ---------------------------------------------------------------------------
#define AQ    0
#define PLANE 9216
#define ABUF  9216
#define STG   (2 * PLANE)       // Kh, Vh
#define ALR   (ABUF + 2 * STG)  // 46080
#define ATOT  (ALR + 512)       // 46592

__global__ __launch_bounds__(256, 2) void attn_tc(float* __restrict__ Outp) {
    extern __shared__ char sm[];
    const uint32_t sb = (uint32_t)__cvta_generic_to_shared(sm);
    const int tid = threadIdx.x, wid = tid >> 5, lane = tid & 31;
    const int g = lane >> 2, t = lane & 3;
    const int qw = wid >> 1, kw = wid & 1;

    const int bid = blockIdx.x;
    int qt, b;
    if (bid < 108)      { qt = bid % 27;            b = bid / 27; }
    else if (bid < 148) { int s = bid - 108;        qt = 27 + (s >> 3); b = s & 7; }
    else                { int p = bid - 148;        qt = 26 - (p % 27); b = (p / 27) + 4; }

    const int q0 = qt * 64;
    const size_t base = (size_t)b * SS;

    // prefetch tile 0 (2 planes x 512 x 16B)
    #pragma unroll
    for (int i = 0; i < 4; i++) {
        int id = tid + i * 256;
        int plane = id >> 9, rem = id & 511;
        int row = rem >> 3, c = rem & 7;
        const __half* src = (plane == 0) ? g_Kh : g_Vh;
        cp16(sb + ABUF + plane * PLANE + row * LDB + c * 16,
             src + (base + row) * HH + c * 8);
    }
    CP_COMMIT();

    // load Q tile to smem, then hoist this warp's Q fragments into registers
    #pragma unroll
    for (int i = 0; i < 2; i++) {
        int id = tid + i * 256;
        int row = id >> 3, c = id & 7;
        *reinterpret_cast<uint4*>(sm + AQ + row * LDB + c * 16) =
            *reinterpret_cast<const uint4*>(g_Qh + (base + q0 + row) * HH + c * 8);
    }
    __syncthreads();
    uint32_t qa[4][4];
    #pragma unroll
    for (int hs = 0; hs < 4; hs++)
        ldm_x4(qa[hs], ldm_addr(sb + AQ, qw * 16, hs * 16));

    float o[8][4];
    #pragma unroll
    for (int i = 0; i < 8; i++)
        #pragma unroll
        for (int j = 0; j < 4; j++) o[i][j] = 0.f;
    float lsum0 = 0.f, lsum1 = 0.f;

    for (int kt = 0; kt <= qt; kt++) {
        const int k0 = kt * 64;
        CP_WAIT0();
        __syncthreads();

        if (kt < qt) {
            const int kn = k0 + 64;
            const uint32_t dstg = sb + ABUF + ((kt + 1) & 1) * STG;
            #pragma unroll
            for (int i = 0; i < 4; i++) {
                int id = tid + i * 256;
                int plane = id >> 9, rem = id & 511;
                int row = rem >> 3, c = rem & 7;
                const __half* src = (plane == 0) ? g_Kh : g_Vh;
                cp16(dstg + plane * PLANE + row * LDB + c * 16,
                     src + (base + kn + row) * HH + c * 8);
            }
        }
        CP_COMMIT();

        const uint32_t stg = sb + ABUF + (kt & 1) * STG;
        const uint32_t sKH = stg, sVH = stg + PLANE;

        // S' = Qh Kh^T (log2 domain)
        float s[4][4];
        #pragma unroll
        for (int i = 0; i < 4; i++)
            #pragma unroll
            for (int j = 0; j < 4; j++) s[i][j] = 0.f;

        #pragma unroll
        for (int hs = 0; hs < 4; hs++) {
            uint32_t bh[4], bh2[4];
            ldm_x4(bh,  ldm_addr_b(sKH, kw * 32,      hs * 16));
            ldm_x4(bh2, ldm_addr_b(sKH, kw * 32 + 16, hs * 16));
            #pragma unroll
            for (int fn = 0; fn < 2; fn++) {
                mma_f16(s[fn],     qa[hs], &bh[fn * 2]);
                mma_f16(s[2 + fn], qa[hs], &bh2[fn * 2]);
            }
        }

        if (kt == qt) {  // causal mask on diagonal tile
            #pragma unroll
            for (int f = 0; f < 4; f++) {
                int kg = k0 + kw * 32 + f * 8 + t * 2;
                int qg0 = q0 + qw * 16 + g, qg1 = qg0 + 8;
                if (kg     > qg0) s[f][0] = -126.f;
                if (kg + 1 > qg0) s[f][1] = -126.f;
                if (kg     > qg1) s[f][2] = -126.f;
                if (kg + 1 > qg1) s[f][3] = -126.f;
            }
        }

        // P = 2^{S'}; row sums; P -> fp16 rn A-fragments
        uint32_t pah[2][4];
        #pragma unroll
        for (int ks2 = 0; ks2 < 2; ks2++) {
            #pragma unroll
            for (int ff = 0; ff < 2; ff++) {
                const int f = ks2 * 2 + ff;
                float p0 = fast_exp2(s[f][0]);
                float p1 = fast_exp2(s[f][1]);
                float p2 = fast_exp2(s[f][2]);
                float p3 = fast_exp2(s[f][3]);
                lsum0 += p0 + p1;
                lsum1 += p2 + p3;
                pah[ks2][ff * 2]     = pack2h(p0, p1);
                pah[ks2][ff * 2 + 1] = pack2h(p2, p3);
            }
        }

        // O += Ph Vh over this warp's k-half, all 64 h columns
        #pragma unroll
        for (int ks2 = 0; ks2 < 2; ks2++) {
            uint32_t vh[4][4];
            #pragma unroll
            for (int c = 0; c < 4; c++)
                ldm_x4_t(vh[c], ldm_addr(sVH, kw * 32 + ks2 * 16, c * 16));
            #pragma unroll
            for (int j = 0; j < 8; j++)
                mma_f16(o[j], pah[ks2], &vh[j >> 1][(j & 1) * 2]);
        }
    }
    __syncthreads();

    lsum0 += __shfl_xor_sync(0xFFFFFFFFu, lsum0, 1);
    lsum0 += __shfl_xor_sync(0xFFFFFFFFu, lsum0, 2);
    lsum1 += __shfl_xor_sync(0xFFFFFFFFu, lsum1, 1);
    lsum1 += __shfl_xor_sync(0xFFFFFFFFu, lsum1, 2);
    float* lred = reinterpret_cast<float*>(sm + ALR);
    if (t == 0) {
        lred[(qw * 2 + kw) * 16 + g]     = lsum0;
        lred[(qw * 2 + kw) * 16 + 8 + g] = lsum1;
    }
    float* ored = reinterpret_cast<float*>(sm);
    if (kw == 1) {
        #pragma unroll
        for (int j = 0; j < 8; j++) {
            int col = j * 8 + t * 2;
            *reinterpret_cast<float2*>(&ored[(qw * 16 + g) * 64 + col]) =
                make_float2(o[j][0], o[j][1]);
            *reinterpret_cast<float2*>(&ored[(qw * 16 + g + 8) * 64 + col]) =
                make_float2(o[j][2], o[j][3]);
        }
    }
    __syncthreads();

    if (kw == 0) {
        float inv0 = 1.f / (lred[(qw * 2) * 16 + g]     + lred[(qw * 2 + 1) * 16 + g]);
        float inv1 = 1.f / (lred[(qw * 2) * 16 + 8 + g] + lred[(qw * 2 + 1) * 16 + 8 + g]);
        #pragma unroll
        for (int j = 0; j < 8; j++) {
            int col = j * 8 + t * 2;
            float2 a0 = *reinterpret_cast<float2*>(&ored[(qw * 16 + g) * 64 + col]);
            float2 a1 = *reinterpret_cast<float2*>(&ored[(qw * 16 + g + 8) * 64 + col]);
            size_t r0 = (base + q0 + qw * 16 + g) * HH + col;
            *reinterpret_cast<float2*>(Outp + r0) =
                make_float2((o[j][0] + a0.x) * inv0, (o[j][1] + a0.y) * inv0);
            *reinterpret_cast<float2*>(Outp + r0 + 8 * HH) =
                make_float2((o[j][2] + a1.x) * inv1, (o[j][3] + a1.y) * inv1);
        }
    }
}

// ---------------------------------------------------------------------------
extern "C" void kernel_launch(void* const* d_in, const int* in_sizes, int n_in,
                              void* d_out, int out_size)
{
    const float* X  = (const float*)d_in[0];
    const float* Wk = (const float*)d_in[1];
    const float* Wq = (const float*)d_in[2];
    const float* Wv = (const float*)d_in[3];
    float* Out = (float*)d_out;
    (void)in_sizes; (void)n_in; (void)out_size;

    cudaFuncSetAttribute(proj_tc, cudaFuncAttributeMaxDynamicSharedMemorySize, PTOT);
    cudaFuncSetAttribute(attn_tc, cudaFuncAttributeMaxDynamicSharedMemorySize, ATOT);

    proj_tc<<<MM / PTM, 256, PTOT>>>(X, Wq, Wk, Wv);
    attn_tc<<<256, 256, ATOT>>>(Out);
}

// round 13
// speedup vs baseline: 1.0646x; 1.0646x over previous
#include <cuda_runtime.h>
#include <cuda_fp16.h>
#include <cstdint>

#define BB 8
#define SS 2048
#define DD 1024
#define HH 64
#define MM (BB*SS)

// Scratch (fp16): Q pre-scaled by log2e/32; K,V hi-only
__device__ __align__(16) __half g_Qh[MM*HH];
__device__ __align__(16) __half g_Kh[MM*HH];
__device__ __align__(16) __half g_Vh[MM*HH];
// W hi (fp16 rn): [3][64][1024], mat order {Q,K,V}
__device__ __align__(16) __half g_Wh[3*HH*DD];

// ---------------------------------------------------------------------------
// helpers
// ---------------------------------------------------------------------------
__device__ __forceinline__ uint32_t pack2h(float lo, float hi) {
    uint32_t r;
    asm("cvt.rn.f16x2.f32 %0, %1, %2;" : "=r"(r) : "f"(hi), "f"(lo));
    return r;
}

__device__ __forceinline__ void ldm_x4(uint32_t* r, uint32_t addr) {
    asm volatile("ldmatrix.sync.aligned.m8n8.x4.shared.b16 {%0,%1,%2,%3}, [%4];"
                 : "=r"(r[0]), "=r"(r[1]), "=r"(r[2]), "=r"(r[3]) : "r"(addr));
}
__device__ __forceinline__ void ldm_x4_t(uint32_t* r, uint32_t addr) {
    asm volatile("ldmatrix.sync.aligned.m8n8.x4.trans.shared.b16 {%0,%1,%2,%3}, [%4];"
                 : "=r"(r[0]), "=r"(r[1]), "=r"(r[2]), "=r"(r[3]) : "r"(addr));
}

__device__ __forceinline__ void cp16(uint32_t dst, const void* src) {
    asm volatile("cp.async.cg.shared.global [%0], [%1], 16;"
                 :: "r"(dst), "l"(src) : "memory");
}
#define CP_COMMIT() asm volatile("cp.async.commit_group;" ::: "memory")
#define CP_WAIT0()  asm volatile("cp.async.wait_group 0;" ::: "memory")

// smem fp16 tiles: row stride 144 bytes (72 halves) -> ldmatrix conflict-free
#define LDB 144

__device__ __forceinline__ uint32_t ldm_addr(uint32_t base, int row0, int col0) {
    int l = threadIdx.x & 31;
    int r = row0 + (l & 7) + ((l >> 3) & 1) * 8;
    int c = col0 + (l >> 4) * 8;
    return base + r * LDB + c * 2;
}
__device__ __forceinline__ uint32_t ldm_addr_b(uint32_t base, int row0, int col0) {
    int l = threadIdx.x & 31;
    int r = row0 + (l & 7) + (l >> 4) * 8;
    int c = col0 + ((l >> 3) & 1) * 8;
    return base + r * LDB + c * 2;
}

__device__ __forceinline__ void mma_f16(float* d, const uint32_t* a, const uint32_t* b) {
    asm volatile(
        "mma.sync.aligned.m16n8k16.row.col.f32.f16.f16.f32 "
        "{%0,%1,%2,%3}, {%4,%5,%6,%7}, {%8,%9}, {%0,%1,%2,%3};"
        : "+f"(d[0]), "+f"(d[1]), "+f"(d[2]), "+f"(d[3])
        : "r"(a[0]), "r"(a[1]), "r"(a[2]), "r"(a[3]), "r"(b[0]), "r"(b[1]));
}

// 2^x via magic-round + deg-4 Taylor. No clamp: inputs bounded (masked = -126).
__device__ __forceinline__ float fast_exp2(float x) {
    float r = x + 12582912.0f;
    int ik = __float_as_int(r) - 0x4B400000;
    float f = x - (r - 12582912.0f);
    float p = fmaf(0.0096180f, f, 0.0555041f);
    p = fmaf(p, f, 0.2402265f);
    p = fmaf(p, f, 0.6931472f);
    p = fmaf(p, f, 1.0f);
    return __int_as_float(__float_as_int(p) + (ik << 23));
}

// ---------------------------------------------------------------------------
// prep_w: convert weights to fp16 (rn). grid (32,3), 8 f32/thread.
// ---------------------------------------------------------------------------
__global__ __launch_bounds__(256) void prep_w(const float* __restrict__ Wq,
                                              const float* __restrict__ Wk,
                                              const float* __restrict__ Wv) {
    int mat = blockIdx.y;
    const float* W = (mat == 0) ? Wq : ((mat == 1) ? Wk : Wv);
    int i = blockIdx.x * 2048 + threadIdx.x * 8;
    float4 v0 = *reinterpret_cast<const float4*>(W + i);
    float4 v1 = *reinterpret_cast<const float4*>(W + i + 4);
    size_t o = ((size_t)mat * HH * DD + i) >> 1;
    uint32_t* ph = reinterpret_cast<uint32_t*>(g_Wh);
    ph[o + 0] = pack2h(v0.x, v0.y);
    ph[o + 1] = pack2h(v0.z, v0.w);
    ph[o + 2] = pack2h(v1.x, v1.y);
    ph[o + 3] = pack2h(v1.z, v1.w);
}

// ---------------------------------------------------------------------------
// proj: Q,K,V = Xh @ Wh^T (1-term fp16). CTA = 64 rows, 256 thr, 256 CTAs.
// Warps 2m x 4n. Outputs fp16 hi-only (Q scaled by log2e/32).
// ---------------------------------------------------------------------------
#define PTM 64
#define PXH 0
#define PWH 9216
#define PTOT 36864

__global__ __launch_bounds__(256) void proj_tc(const float* __restrict__ X) {
    extern __shared__ char sm[];
    const uint32_t sb = (uint32_t)__cvta_generic_to_shared(sm);
    const int tid = threadIdx.x, wid = tid >> 5, lane = tid & 31;
    const int g = lane >> 2, t = lane & 3;
    const int wm = wid >> 2, wn = wid & 3;
    const int m0 = blockIdx.x * PTM;

    float acc[3][2][2][4];
    #pragma unroll
    for (int a = 0; a < 3; a++)
        #pragma unroll
        for (int b = 0; b < 2; b++)
            #pragma unroll
            for (int c = 0; c < 2; c++)
                #pragma unroll
                for (int d = 0; d < 4; d++) acc[a][b][c][d] = 0.f;

    for (int kc = 0; kc < 16; kc++) {
        const int kbase = kc * 64;
        #pragma unroll
        for (int i = 0; i < 4; i++) {
            int id = tid + i * 256;
            int row = id >> 4, c4 = id & 15;
            float4 v = *reinterpret_cast<const float4*>(
                X + (size_t)(m0 + row) * DD + kbase + c4 * 4);
            uint32_t off = row * LDB + c4 * 8;
            *reinterpret_cast<uint32_t*>(sm + PXH + off)     = pack2h(v.x, v.y);
            *reinterpret_cast<uint32_t*>(sm + PXH + off + 4) = pack2h(v.z, v.w);
        }
        #pragma unroll
        for (int i = 0; i < 6; i++) {
            int id = tid + i * 256;
            int row = id >> 3, c = id & 7;
            uint4 v = *reinterpret_cast<const uint4*>(g_Wh + (size_t)row * DD + kbase + c * 8);
            *reinterpret_cast<uint4*>(sm + PWH + row * LDB + c * 16) = v;
        }
        __syncthreads();

        #pragma unroll
        for (int ks = 0; ks < 4; ks++) {
            uint32_t ah[2][4];
            #pragma unroll
            for (int fm = 0; fm < 2; fm++)
                ldm_x4(ah[fm], ldm_addr(sb + PXH, wm * 32 + fm * 16, ks * 16));
            #pragma unroll
            for (int mat = 0; mat < 3; mat++) {
                uint32_t bh[4];
                ldm_x4(bh, ldm_addr_b(sb + PWH, mat * 64 + wn * 16, ks * 16));
                #pragma unroll
                for (int fm = 0; fm < 2; fm++)
                    #pragma unroll
                    for (int fn = 0; fn < 2; fn++)
                        mma_f16(acc[mat][fm][fn], ah[fm], &bh[fn * 2]);
            }
        }
        __syncthreads();
    }

    #pragma unroll
    for (int mat = 0; mat < 3; mat++) {
        __half* gh = (mat == 0) ? g_Qh : ((mat == 1) ? g_Kh : g_Vh);
        const float scl = (mat == 0) ? (1.44269504f / 32.0f) : 1.0f;
        #pragma unroll
        for (int fm = 0; fm < 2; fm++)
            #pragma unroll
            for (int fn = 0; fn < 2; fn++) {
                const float* c = acc[mat][fm][fn];
                int r0 = m0 + wm * 32 + fm * 16 + g;
                int col = wn * 16 + fn * 8 + t * 2;
                reinterpret_cast<uint32_t*>(gh)[((size_t)r0 * HH + col) >> 1] =
                    pack2h(c[0] * scl, c[1] * scl);
                reinterpret_cast<uint32_t*>(gh)[((size_t)(r0 + 8) * HH + col) >> 1] =
                    pack2h(c[2] * scl, c[3] * scl);
            }
    }
}

// ---------------------------------------------------------------------------
// attn: flash attention (fp16 hi-only), no-max softmax, register P, hoisted Q.
// CTA = 32 query rows, 128 threads (warps 2 qw x 2 kw), grid 512 = single
// wave at occ 4. LPT snake schedule over bid%148 rounds. Lower-half diagonal
// kw=1 warp skips its fully-masked block.
// ---------------------------------------------------------------------------
#define AQ    0
#define ABUF  4608              // Q: 32 rows x 144 B
#define PLANE 9216
#define STG   (2 * PLANE)       // Kh, Vh
#define ALR   (ABUF + 2 * STG)  // 41472
#define ATOT  (ALR + 256)       // 41728

__global__ __launch_bounds__(128, 4) void attn_tc(float* __restrict__ Outp) {
    extern __shared__ char sm[];
    const uint32_t sb = (uint32_t)__cvta_generic_to_shared(sm);
    const int tid = threadIdx.x, wid = tid >> 5, lane = tid & 31;
    const int g = lane >> 2, t = lane & 3;
    const int qw = wid >> 1, kw = wid & 1;

    // LPT snake: items sorted desc by qt; rounds of 148 map to the same SM set.
    const int bid = blockIdx.x;
    int r = bid / 148, j = bid - r * 148;
    int i = (r < 3) ? (r * 148 + ((r & 1) ? (147 - j) : j)) : bid;
    const int qt = 31 - (i >> 4);
    const int sub = i & 15;
    const int b = sub >> 1, half = sub & 1;

    const int q0c = qt * 64 + half * 32;   // this CTA's 32 query rows
    const size_t base = (size_t)b * SS;

    // prefetch K/V tile 0 (2 planes x 512 lines, 8 cp16/thread)
    #pragma unroll
    for (int i2 = 0; i2 < 8; i2++) {
        int id = tid + i2 * 128;
        int plane = id >> 9, rem = id & 511;
        int row = rem >> 3, c = rem & 7;
        const __half* src = (plane == 0) ? g_Kh : g_Vh;
        cp16(sb + ABUF + plane * PLANE + row * LDB + c * 16,
             src + (base + row) * HH + c * 8);
    }
    CP_COMMIT();

    // load Q tile (32 rows) to smem, hoist this warp's fragments
    #pragma unroll
    for (int i2 = 0; i2 < 2; i2++) {
        int id = tid + i2 * 128;
        int row = id >> 3, c = id & 7;
        *reinterpret_cast<uint4*>(sm + AQ + row * LDB + c * 16) =
            *reinterpret_cast<const uint4*>(g_Qh + (base + q0c + row) * HH + c * 8);
    }
    __syncthreads();
    uint32_t qa[4][4];
    #pragma unroll
    for (int hs = 0; hs < 4; hs++)
        ldm_x4(qa[hs], ldm_addr(sb + AQ, qw * 16, hs * 16));

    float o[8][4];
    #pragma unroll
    for (int i2 = 0; i2 < 8; i2++)
        #pragma unroll
        for (int j2 = 0; j2 < 4; j2++) o[i2][j2] = 0.f;
    float lsum0 = 0.f, lsum1 = 0.f;

    for (int kt = 0; kt <= qt; kt++) {
        const int k0 = kt * 64;
        CP_WAIT0();
        __syncthreads();

        if (kt < qt) {
            const int kn = k0 + 64;
            const uint32_t dstg = sb + ABUF + ((kt + 1) & 1) * STG;
            #pragma unroll
            for (int i2 = 0; i2 < 8; i2++) {
                int id = tid + i2 * 128;
                int plane = id >> 9, rem = id & 511;
                int row = rem >> 3, c = rem & 7;
                const __half* src = (plane == 0) ? g_Kh : g_Vh;
                cp16(dstg + plane * PLANE + row * LDB + c * 16,
                     src + (base + kn + row) * HH + c * 8);
            }
        }
        CP_COMMIT();

        // lower half-tile, diagonal: kw=1's 32 k-cols are all > every row -> skip
        if (kt == qt && half == 0 && kw == 1) continue;

        const uint32_t stg = sb + ABUF + (kt & 1) * STG;
        const uint32_t sKH = stg, sVH = stg + PLANE;

        // S' = Qh Kh^T (log2 domain)
        float s[4][4];
        #pragma unroll
        for (int i2 = 0; i2 < 4; i2++)
            #pragma unroll
            for (int j2 = 0; j2 < 4; j2++) s[i2][j2] = 0.f;

        #pragma unroll
        for (int hs = 0; hs < 4; hs++) {
            uint32_t bh[4], bh2[4];
            ldm_x4(bh,  ldm_addr_b(sKH, kw * 32,      hs * 16));
            ldm_x4(bh2, ldm_addr_b(sKH, kw * 32 + 16, hs * 16));
            #pragma unroll
            for (int fn = 0; fn < 2; fn++) {
                mma_f16(s[fn],     qa[hs], &bh[fn * 2]);
                mma_f16(s[2 + fn], qa[hs], &bh2[fn * 2]);
            }
        }

        if (kt == qt) {  // causal mask on diagonal tile
            #pragma unroll
            for (int f = 0; f < 4; f++) {
                int kg = k0 + kw * 32 + f * 8 + t * 2;
                int qg0 = q0c + qw * 16 + g, qg1 = qg0 + 8;
                if (kg     > qg0) s[f][0] = -126.f;
                if (kg + 1 > qg0) s[f][1] = -126.f;
                if (kg     > qg1) s[f][2] = -126.f;
                if (kg + 1 > qg1) s[f][3] = -126.f;
            }
        }

        // P = 2^{S'}; row sums; P -> fp16 rn A-fragments
        uint32_t pah[2][4];
        #pragma unroll
        for (int ks2 = 0; ks2 < 2; ks2++) {
            #pragma unroll
            for (int ff = 0; ff < 2; ff++) {
                const int f = ks2 * 2 + ff;
                float p0 = fast_exp2(s[f][0]);
                float p1 = fast_exp2(s[f][1]);
                float p2 = fast_exp2(s[f][2]);
                float p3 = fast_exp2(s[f][3]);
                lsum0 += p0 + p1;
                lsum1 += p2 + p3;
                pah[ks2][ff * 2]     = pack2h(p0, p1);
                pah[ks2][ff * 2 + 1] = pack2h(p2, p3);
            }
        }

        // O += Ph Vh over this warp's k-half, all 64 h columns
        #pragma unroll
        for (int ks2 = 0; ks2 < 2; ks2++) {
            uint32_t vh[4][4];
            #pragma unroll
            for (int c = 0; c < 4; c++)
                ldm_x4_t(vh[c], ldm_addr(sVH, kw * 32 + ks2 * 16, c * 16));
            #pragma unroll
            for (int j2 = 0; j2 < 8; j2++)
                mma_f16(o[j2], pah[ks2], &vh[j2 >> 1][(j2 & 1) * 2]);
        }
    }
    __syncthreads();

    // lsum reduction across quad -> lred[qw][kw][16]
    lsum0 += __shfl_xor_sync(0xFFFFFFFFu, lsum0, 1);
    lsum0 += __shfl_xor_sync(0xFFFFFFFFu, lsum0, 2);
    lsum1 += __shfl_xor_sync(0xFFFFFFFFu, lsum1, 1);
    lsum1 += __shfl_xor_sync(0xFFFFFFFFu, lsum1, 2);
    float* lred = reinterpret_cast<float*>(sm + ALR);
    if (t == 0) {
        lred[(qw * 2 + kw) * 16 + g]     = lsum0;
        lred[(qw * 2 + kw) * 16 + 8 + g] = lsum1;
    }
    // kw==1 warps dump O into reduction buffer (reuses dead tile smem)
    float* ored = reinterpret_cast<float*>(sm);  // [qw][16][64]
    if (kw == 1) {
        #pragma unroll
        for (int j2 = 0; j2 < 8; j2++) {
            int col = j2 * 8 + t * 2;
            *reinterpret_cast<float2*>(&ored[(qw * 16 + g) * 64 + col]) =
                make_float2(o[j2][0], o[j2][1]);
            *reinterpret_cast<float2*>(&ored[(qw * 16 + g + 8) * 64 + col]) =
                make_float2(o[j2][2], o[j2][3]);
        }
    }
    __syncthreads();

    if (kw == 0) {
        float inv0 = 1.f / (lred[(qw * 2) * 16 + g]     + lred[(qw * 2 + 1) * 16 + g]);
        float inv1 = 1.f / (lred[(qw * 2) * 16 + 8 + g] + lred[(qw * 2 + 1) * 16 + 8 + g]);
        #pragma unroll
        for (int j2 = 0; j2 < 8; j2++) {
            int col = j2 * 8 + t * 2;
            float2 a0 = *reinterpret_cast<float2*>(&ored[(qw * 16 + g) * 64 + col]);
            float2 a1 = *reinterpret_cast<float2*>(&ored[(qw * 16 + g + 8) * 64 + col]);
            size_t r0 = (base + q0c + qw * 16 + g) * HH + col;
            *reinterpret_cast<float2*>(Outp + r0) =
                make_float2((o[j2][0] + a0.x) * inv0, (o[j2][1] + a0.y) * inv0);
            *reinterpret_cast<float2*>(Outp + r0 + 8 * HH) =
                make_float2((o[j2][2] + a1.x) * inv1, (o[j2][3] + a1.y) * inv1);
        }
    }
}

// ---------------------------------------------------------------------------
extern "C" void kernel_launch(void* const* d_in, const int* in_sizes, int n_in,
                              void* d_out, int out_size)
{
    const float* X  = (const float*)d_in[0];
    const float* Wk = (const float*)d_in[1];
    const float* Wq = (const float*)d_in[2];
    const float* Wv = (const float*)d_in[3];
    float* Out = (float*)d_out;
    (void)in_sizes; (void)n_in; (void)out_size;

    cudaFuncSetAttribute(proj_tc, cudaFuncAttributeMaxDynamicSharedMemorySize, PTOT);
    cudaFuncSetAttribute(attn_tc, cudaFuncAttributeMaxDynamicSharedMemorySize, ATOT);

    prep_w<<<dim3(32, 3), 256>>>(Wq, Wk, Wv);
    proj_tc<<<MM / PTM, 256, PTOT>>>(X);
    attn_tc<<<512, 128, ATOT>>>(Out);
}